// round 2
// baseline (speedup 1.0000x reference)
#include <cuda_runtime.h>
#include <cstdint>

// Problem constants
#define TT   512      // sequence length
#define EE   1024     // embedding dim
#define HDIM 512      // per-direction hidden
#define G4   2048     // 4*HDIM gate rows
#define KTAG 32       // tags
#define NEGV (-10000.0f)
#define START_TAG 30
#define STOP_TAG  31

// LSTM recurrent kernel config
#define NBD  64              // blocks per direction
#define JPB  (HDIM / NBD)    // h-indices per block = 8
#define LSTM_THREADS 256

// ---------------- scratch (device globals; no allocation) ----------------
__device__ float g_xw[2][TT][G4];        // input projections + biases, 8 MB
                                         // g_xw[dir][s] = proj of the token
                                         // consumed at scan step s of dir
__device__ float g_lstm[TT][2 * HDIM];   // concatenated [hf | hb], 2 MB
__device__ float g_feats[TT][KTAG];      // tag scores
__device__ int   g_cnt[2];               // per-direction step barrier counters

// ---------------- reset barrier counters each launch ----------------
__global__ void reset_kernel() { g_cnt[0] = 0; g_cnt[1] = 0; }

// ---------------- Kernel A: fused embed-gather + input projection GEMM ----
// g_xw[dir][s][r] = embed[token consumed at scan step s of dir] . w_ih[r]
//                   + b_ih[r] + b_hh[r]
// dir==1 consumes the sentence reversed, so s -> sentence[TT-1-s].
__global__ __launch_bounds__(256) void gemm_xw_kernel(
    const int* __restrict__ sentence,
    const float* __restrict__ embed,
    const float* __restrict__ w_ih_f, const float* __restrict__ b_ih_f,
    const float* __restrict__ b_hh_f,
    const float* __restrict__ w_ih_b, const float* __restrict__ b_ih_b,
    const float* __restrict__ b_hh_b)
{
    int dir = blockIdx.z;
    const float* W  = dir ? w_ih_b : w_ih_f;
    const float* Bi = dir ? b_ih_b : b_ih_f;
    const float* Bh = dir ? b_hh_b : b_hh_f;

    int n0 = blockIdx.x * 64;   // gate-row tile
    int m0 = blockIdx.y * 64;   // scan-step tile

    __shared__ float As[16][64];
    __shared__ float Bs[16][64];

    int tid = threadIdx.x;
    int tx = tid & 15;          // 0..15 -> 4 output cols each
    int ty = tid >> 4;          // 0..15 -> 4 output rows each

    int lrow = tid >> 2;        // 0..63  load row within tile
    int lk4  = tid & 3;         // which float4 of the 16-wide k slab

    int sglob = m0 + lrow;                     // scan step
    int sidx  = dir ? (TT - 1 - sglob) : sglob; // token index consumed there
    const float* aptr = embed + (size_t)sentence[sidx] * EE + lk4 * 4;
    const float* bptr = W + (size_t)(n0 + lrow) * EE + lk4 * 4;

    float acc[4][4];
#pragma unroll
    for (int i = 0; i < 4; i++)
#pragma unroll
        for (int j = 0; j < 4; j++) acc[i][j] = 0.f;

    for (int k0 = 0; k0 < EE; k0 += 16) {
        float4 av = *(const float4*)(aptr + k0);
        float4 bv = *(const float4*)(bptr + k0);
        __syncthreads();
        As[lk4 * 4 + 0][lrow] = av.x; As[lk4 * 4 + 1][lrow] = av.y;
        As[lk4 * 4 + 2][lrow] = av.z; As[lk4 * 4 + 3][lrow] = av.w;
        Bs[lk4 * 4 + 0][lrow] = bv.x; Bs[lk4 * 4 + 1][lrow] = bv.y;
        Bs[lk4 * 4 + 2][lrow] = bv.z; Bs[lk4 * 4 + 3][lrow] = bv.w;
        __syncthreads();
#pragma unroll
        for (int k = 0; k < 16; k++) {
            float4 a4 = ((const float4*)As[k])[ty];
            float4 b4 = ((const float4*)Bs[k])[tx];
            float a[4] = {a4.x, a4.y, a4.z, a4.w};
            float b[4] = {b4.x, b4.y, b4.z, b4.w};
#pragma unroll
            for (int i = 0; i < 4; i++)
#pragma unroll
                for (int j = 0; j < 4; j++) acc[i][j] += a[i] * b[j];
        }
    }

#pragma unroll
    for (int i = 0; i < 4; i++) {
        int m = m0 + ty * 4 + i;
#pragma unroll
        for (int j = 0; j < 4; j++) {
            int r = n0 + tx * 4 + j;
            g_xw[dir][m][r] = acc[i][j] + Bi[r] + Bh[r];
        }
    }
}

// ---------------- Kernel B: persistent recurrent LSTM (both directions) ----
// 64 blocks per direction; each block keeps its 4*JPB rows of w_hh resident
// in SMEM for all 512 steps. Global counter barrier per step per direction.
__global__ __launch_bounds__(LSTM_THREADS, 1) void lstm_kernel(
    const float* __restrict__ w_hh_f,
    const float* __restrict__ w_hh_b,
    const float* __restrict__ h0,
    const float* __restrict__ c0)
{
    extern __shared__ float sm[];
    float* ws   = sm;             // 4*JPB*HDIM = 16384 floats (64 KB)
    float* hbuf = sm + 16384;     // 512
    float* gbuf = sm + 16896;     // 32
    float* c_s  = sm + 16928;     // JPB

    int bid = blockIdx.x;
    int dir = bid / NBD;
    int blk = bid % NBD;
    int j0  = blk * JPB;
    int tid = threadIdx.x;

    const float* w_hh = dir ? w_hh_b : w_hh_f;

    // Load this block's weight slice (coalesced float4)
    for (int idx4 = tid; idx4 < 4 * JPB * (HDIM / 4); idx4 += LSTM_THREADS) {
        int r  = idx4 >> 7;       // local row 0..31  (gi*JPB + jj)
        int k4 = idx4 & 127;
        int gi = r >> 3;
        int jj = r & 7;
        ((float4*)ws)[idx4] =
            *((const float4*)(w_hh + (size_t)(gi * HDIM + j0 + jj) * HDIM) + k4);
    }
    if (tid < JPB) c_s[tid] = c0[dir * HDIM + j0 + tid];
    __syncthreads();

    int lane8 = tid & 7;
    int task  = tid >> 3;         // 0..31 = (gate gi)*8 + jj
    int gi    = task >> 3;
    int jj    = task & 7;
    const float4* wrow4 = (const float4*)(ws + task * HDIM);
    volatile int* cnt = (volatile int*)&g_cnt[dir];

    for (int s = 0; s < TT; s++) {
        int t = dir ? (TT - 1 - s) : s;   // token/time index this step writes
        const float* hsrc;
        if (s == 0)      hsrc = h0 + dir * HDIM;
        else if (dir == 0) hsrc = &g_lstm[s - 1][0];
        else               hsrc = &g_lstm[TT - s][HDIM];

        for (int k = tid; k < HDIM; k += LSTM_THREADS)
            hbuf[k] = __ldcg(hsrc + k);

        float xwv = 0.f;
        // NOTE: g_xw is scan-step indexed — read [s], NOT [t].
        if (lane8 == 0) xwv = g_xw[dir][s][gi * HDIM + j0 + jj];
        __syncthreads();

        float acc = 0.f;
        const float4* h4 = (const float4*)hbuf;
#pragma unroll
        for (int i = 0; i < 16; i++) {
            float4 w = wrow4[lane8 + 8 * i];
            float4 h = h4[lane8 + 8 * i];
            acc += w.x * h.x;
            acc += w.y * h.y;
            acc += w.z * h.z;
            acc += w.w * h.w;
        }
        acc += __shfl_down_sync(0xffffffffu, acc, 4, 8);
        acc += __shfl_down_sync(0xffffffffu, acc, 2, 8);
        acc += __shfl_down_sync(0xffffffffu, acc, 1, 8);
        if (lane8 == 0) gbuf[task] = acc + xwv;
        __syncthreads();

        if (tid < JPB) {
            float iv = gbuf[0 * 8 + tid];
            float fg = gbuf[1 * 8 + tid];
            float gv = gbuf[2 * 8 + tid];
            float ov = gbuf[3 * 8 + tid];
            float si = 1.f / (1.f + expf(-iv));
            float sf = 1.f / (1.f + expf(-fg));
            float so = 1.f / (1.f + expf(-ov));
            float c  = sf * c_s[tid] + si * tanhf(gv);
            c_s[tid] = c;
            g_lstm[t][dir * HDIM + j0 + tid] = so * tanhf(c);
        }
        __threadfence();
        __syncthreads();
        if (tid == 0) {
            atomicAdd(&g_cnt[dir], 1);
            int target = (s + 1) * NBD;
            while (*cnt < target) { }
            __threadfence();
        }
        __syncthreads();
    }
}

// ---------------- Kernel C: tag projection ----------------
__global__ __launch_bounds__(256) void tag_kernel(
    const float* __restrict__ w_tag, const float* __restrict__ b_tag)
{
    int t = blockIdx.x;
    __shared__ float row[2 * HDIM];
    int tid = threadIdx.x; // 256
    ((float4*)row)[tid] = ((const float4*)&g_lstm[t][0])[tid];
    __syncthreads();

    int lane8 = tid & 7;
    int k = tid >> 3;     // 0..31
    const float4* wr = (const float4*)(w_tag + (size_t)k * 2 * HDIM);
    const float4* r4 = (const float4*)row;
    float acc = 0.f;
#pragma unroll
    for (int i = 0; i < 32; i++) {
        float4 w = wr[lane8 + 8 * i];
        float4 x = r4[lane8 + 8 * i];
        acc += w.x * x.x;
        acc += w.y * x.y;
        acc += w.z * x.z;
        acc += w.w * x.w;
    }
    acc += __shfl_down_sync(0xffffffffu, acc, 4, 8);
    acc += __shfl_down_sync(0xffffffffu, acc, 2, 8);
    acc += __shfl_down_sync(0xffffffffu, acc, 1, 8);
    if (lane8 == 0) g_feats[t][k] = acc + b_tag[k];
}

// ---------------- Kernel D: Viterbi decode (one warp) ----------------
__global__ void viterbi_kernel(const float* __restrict__ trans,
                               float* __restrict__ out)
{
    __shared__ float fv[KTAG];
    __shared__ unsigned char bp[TT][KTAG];
    int tid = threadIdx.x;  // 32, thread = next-tag index

    float tr[KTAG];
#pragma unroll
    for (int p = 0; p < KTAG; p++) tr[p] = trans[tid * KTAG + p];
    float stoprow = trans[STOP_TAG * KTAG + tid];

    fv[tid] = (tid == START_TAG) ? 0.f : NEGV;
    __syncwarp();

    for (int t = 0; t < TT; t++) {
        float best = -3.4e38f;
        int bi = 0;
#pragma unroll
        for (int p = 0; p < KTAG; p++) {
            float sc = fv[p] + tr[p];
            if (sc > best) { best = sc; bi = p; }
        }
        bp[t][tid] = (unsigned char)bi;
        float nf = best + g_feats[t][tid];
        __syncwarp();
        fv[tid] = nf;
        __syncwarp();
    }

    float tv = fv[tid] + stoprow;
    float bv = tv;
    int bidx = tid;
#pragma unroll
    for (int off = 16; off > 0; off >>= 1) {
        float ov = __shfl_down_sync(0xffffffffu, bv, off);
        int oi   = __shfl_down_sync(0xffffffffu, bidx, off);
        if (ov > bv || (ov == bv && oi < bidx)) { bv = ov; bidx = oi; }
    }
    bv   = __shfl_sync(0xffffffffu, bv, 0);
    bidx = __shfl_sync(0xffffffffu, bidx, 0);

    if (tid == 0) {
        out[0] = bv;                     // score
        out[TT] = (float)bidx;           // path[T-1] = best
        int tag = bidx;
        for (int t = TT - 1; t >= 1; t--) {
            tag = bp[t][tag];
            out[t] = (float)tag;         // path[t-1]
        }
    }
}

// ---------------- launch ----------------
extern "C" void kernel_launch(void* const* d_in, const int* in_sizes, int n_in,
                              void* d_out, int out_size)
{
    const int*   sentence = (const int*)d_in[0];
    const float* embed    = (const float*)d_in[1];
    const float* w_ih_f   = (const float*)d_in[2];
    const float* w_hh_f   = (const float*)d_in[3];
    const float* b_ih_f   = (const float*)d_in[4];
    const float* b_hh_f   = (const float*)d_in[5];
    const float* w_ih_b   = (const float*)d_in[6];
    const float* w_hh_b   = (const float*)d_in[7];
    const float* b_ih_b   = (const float*)d_in[8];
    const float* b_hh_b   = (const float*)d_in[9];
    const float* h0       = (const float*)d_in[10];
    const float* c0       = (const float*)d_in[11];
    const float* w_tag    = (const float*)d_in[12];
    const float* b_tag    = (const float*)d_in[13];
    const float* trans    = (const float*)d_in[14];
    float* out = (float*)d_out;

    reset_kernel<<<1, 1>>>();

    dim3 ggrid(G4 / 64, TT / 64, 2);
    gemm_xw_kernel<<<ggrid, 256>>>(sentence, embed,
                                   w_ih_f, b_ih_f, b_hh_f,
                                   w_ih_b, b_ih_b, b_hh_b);

    const int smem_bytes = (16384 + 512 + 32 + JPB) * 4;
    cudaFuncSetAttribute(lstm_kernel,
                         cudaFuncAttributeMaxDynamicSharedMemorySize,
                         smem_bytes);
    lstm_kernel<<<2 * NBD, LSTM_THREADS, smem_bytes>>>(w_hh_f, w_hh_b, h0, c0);

    tag_kernel<<<TT, 256>>>(w_tag, b_tag);

    viterbi_kernel<<<1, 32>>>(trans, out);
}

// round 3
// speedup vs baseline: 1.1253x; 1.1253x over previous
#include <cuda_runtime.h>
#include <cstdint>

// Problem constants
#define TT   512      // sequence length
#define EE   1024     // embedding dim
#define HDIM 512      // per-direction hidden
#define G4   2048     // 4*HDIM gate rows
#define KTAG 32       // tags
#define NEGV (-10000.0f)
#define START_TAG 30
#define STOP_TAG  31

// LSTM recurrent kernel config
#define NBD  64              // blocks per direction
#define JPB  (HDIM / NBD)    // h-indices per block = 8
#define LSTM_THREADS 256

// ---------------- scratch (device globals; no allocation) ----------------
__device__ float g_xw[2][TT][G4];        // input projections + biases (scan-step indexed)
__device__ float g_lstm[TT][2 * HDIM];   // concatenated [hf | hb]
__device__ float g_feats[TT][KTAG];      // tag scores
__device__ volatile int g_flag[2][NBD * 32];  // per-block step flags, 128B stride

// ---------------- reset flags each launch ----------------
__global__ void reset_kernel() {
    int t = threadIdx.x;           // 128 threads
    if (t < 64)       g_flag[0][t * 32] = 0;
    else              g_flag[1][(t - 64) * 32] = 0;
}

// ---------------- Kernel A: embed-gather + input projection GEMM ---------
// 128x128 output tile per block, 8x8 per thread, K-slab 8, fp32.
// g_xw[dir][s][r] = embed[token at scan step s of dir] . w_ih[r] + b_ih[r] + b_hh[r]
__global__ __launch_bounds__(256, 1) void gemm_xw_kernel(
    const int* __restrict__ sentence,
    const float* __restrict__ embed,
    const float* __restrict__ w_ih_f, const float* __restrict__ b_ih_f,
    const float* __restrict__ b_hh_f,
    const float* __restrict__ w_ih_b, const float* __restrict__ b_ih_b,
    const float* __restrict__ b_hh_b)
{
    int dir = blockIdx.z;
    const float* W  = dir ? w_ih_b : w_ih_f;
    const float* Bi = dir ? b_ih_b : b_ih_f;
    const float* Bh = dir ? b_hh_b : b_hh_f;

    int n0 = blockIdx.x * 128;   // gate-row tile
    int m0 = blockIdx.y * 128;   // scan-step tile

    __shared__ __align__(16) float As[8][128];
    __shared__ __align__(16) float Bs[8][128];

    int tid = threadIdx.x;
    int tx = tid & 15;           // 0..15 -> 8 output cols
    int ty = tid >> 4;           // 0..15 -> 8 output rows

    int lrow = tid >> 1;         // 0..127 load row
    int lq   = tid & 1;          // which float4 of the 8-wide k slab

    int sglob = m0 + lrow;                       // scan step
    int sidx  = dir ? (TT - 1 - sglob) : sglob;  // token consumed there
    const float* aptr = embed + (size_t)sentence[sidx] * EE + lq * 4;
    const float* bptr = W + (size_t)(n0 + lrow) * EE + lq * 4;

    float acc[8][8];
#pragma unroll
    for (int i = 0; i < 8; i++)
#pragma unroll
        for (int j = 0; j < 8; j++) acc[i][j] = 0.f;

    float4 a_nx = *(const float4*)aptr;
    float4 b_nx = *(const float4*)bptr;

    for (int k0 = 0; k0 < EE; k0 += 8) {
        As[lq * 4 + 0][lrow] = a_nx.x; As[lq * 4 + 1][lrow] = a_nx.y;
        As[lq * 4 + 2][lrow] = a_nx.z; As[lq * 4 + 3][lrow] = a_nx.w;
        Bs[lq * 4 + 0][lrow] = b_nx.x; Bs[lq * 4 + 1][lrow] = b_nx.y;
        Bs[lq * 4 + 2][lrow] = b_nx.z; Bs[lq * 4 + 3][lrow] = b_nx.w;
        __syncthreads();

        if (k0 + 8 < EE) {
            a_nx = *(const float4*)(aptr + k0 + 8);
            b_nx = *(const float4*)(bptr + k0 + 8);
        }

#pragma unroll
        for (int k = 0; k < 8; k++) {
            float4 a0 = ((const float4*)As[k])[ty * 2];
            float4 a1 = ((const float4*)As[k])[ty * 2 + 1];
            float4 b0 = ((const float4*)Bs[k])[tx * 2];
            float4 b1 = ((const float4*)Bs[k])[tx * 2 + 1];
            float a[8] = {a0.x, a0.y, a0.z, a0.w, a1.x, a1.y, a1.z, a1.w};
            float b[8] = {b0.x, b0.y, b0.z, b0.w, b1.x, b1.y, b1.z, b1.w};
#pragma unroll
            for (int i = 0; i < 8; i++)
#pragma unroll
                for (int j = 0; j < 8; j++)
                    acc[i][j] = fmaf(a[i], b[j], acc[i][j]);
        }
        __syncthreads();
    }

    // epilogue with bias
    int rbase = n0 + tx * 8;
    float4 bi0 = *(const float4*)(Bi + rbase);
    float4 bi1 = *(const float4*)(Bi + rbase + 4);
    float4 bh0 = *(const float4*)(Bh + rbase);
    float4 bh1 = *(const float4*)(Bh + rbase + 4);
    float bias[8] = {bi0.x + bh0.x, bi0.y + bh0.y, bi0.z + bh0.z, bi0.w + bh0.w,
                     bi1.x + bh1.x, bi1.y + bh1.y, bi1.z + bh1.z, bi1.w + bh1.w};
#pragma unroll
    for (int i = 0; i < 8; i++) {
        int m = m0 + ty * 8 + i;
        float4 o0 = make_float4(acc[i][0] + bias[0], acc[i][1] + bias[1],
                                acc[i][2] + bias[2], acc[i][3] + bias[3]);
        float4 o1 = make_float4(acc[i][4] + bias[4], acc[i][5] + bias[5],
                                acc[i][6] + bias[6], acc[i][7] + bias[7]);
        *(float4*)&g_xw[dir][m][rbase]     = o0;
        *(float4*)&g_xw[dir][m][rbase + 4] = o1;
    }
}

// ---------------- Kernel B: persistent recurrent LSTM --------------------
// 64 blocks/dir; weights live in REGISTERS (64 floats/thread).
// Flag-based step barrier: no atomics, per-block 128B-strided flag words.
__global__ __launch_bounds__(LSTM_THREADS, 1) void lstm_kernel(
    const float* __restrict__ w_hh_f,
    const float* __restrict__ w_hh_b,
    const float* __restrict__ h0,
    const float* __restrict__ c0)
{
    __shared__ __align__(16) float hbuf[HDIM];
    __shared__ float gbuf[32];
    __shared__ float c_s[JPB];

    int bid = blockIdx.x;
    int dir = bid / NBD;
    int blk = bid % NBD;
    int j0  = blk * JPB;
    int tid = threadIdx.x;
    int lane8 = tid & 7;
    int task  = tid >> 3;        // 0..31 = gi*8 + jj
    int gi    = task >> 3;
    int jj    = task & 7;

    const float* w_hh = dir ? w_hh_b : w_hh_f;

    // Weights into registers: row gi*HDIM + j0 + jj, float4 cols lane8 + 8*i
    const float4* wrow = (const float4*)(w_hh + (size_t)(gi * HDIM + j0 + jj) * HDIM);
    float4 w[16];
#pragma unroll
    for (int i = 0; i < 16; i++) w[i] = wrow[lane8 + 8 * i];

    if (tid < JPB) c_s[tid] = c0[dir * HDIM + j0 + tid];
    __syncthreads();

    volatile int* flags = g_flag[dir];

    for (int s = 0; s < TT; s++) {
        int t = dir ? (TT - 1 - s) : s;
        const float* hsrc;
        if (s == 0)        hsrc = h0 + dir * HDIM;
        else if (dir == 0) hsrc = &g_lstm[s - 1][0];
        else               hsrc = &g_lstm[TT - s][HDIM];

        if (tid < 128)
            ((float4*)hbuf)[tid] = __ldcg((const float4*)hsrc + tid);

        float xwv = 0.f;
        if (lane8 == 0) xwv = __ldcg(&g_xw[dir][s][gi * HDIM + j0 + jj]);
        __syncthreads();

        // h . w_row  (h LDS is 4-way broadcast within warp -> 1 wavefront each)
        float acc = 0.f;
        const float4* h4 = (const float4*)hbuf;
#pragma unroll
        for (int i = 0; i < 16; i++) {
            float4 h = h4[lane8 + 8 * i];
            acc = fmaf(w[i].x, h.x, acc);
            acc = fmaf(w[i].y, h.y, acc);
            acc = fmaf(w[i].z, h.z, acc);
            acc = fmaf(w[i].w, h.w, acc);
        }
        acc += __shfl_down_sync(0xffffffffu, acc, 4, 8);
        acc += __shfl_down_sync(0xffffffffu, acc, 2, 8);
        acc += __shfl_down_sync(0xffffffffu, acc, 1, 8);
        if (lane8 == 0) gbuf[task] = acc + xwv;
        __syncthreads();

        // activations across warp 0: lane = gate*8 + jj
        if (tid < 32) {
            float gval = gbuf[tid];
            float act;
            if ((tid >> 3) == 2) act = tanhf(gval);                 // g gate
            else                 act = 1.f / (1.f + expf(-gval));   // i,f,o
            float xf = __shfl_sync(0xffffffffu, act, tid + 8);
            float xg = __shfl_sync(0xffffffffu, act, tid + 16);
            float xo = __shfl_sync(0xffffffffu, act, tid + 24);
            if (tid < JPB) {
                float c = fmaf(xf, c_s[tid], act * xg);  // act = sigmoid(i)
                c_s[tid] = c;
                float hv = xo * tanhf(c);
                __stcg(&g_lstm[t][dir * HDIM + j0 + tid], hv);
                __threadfence();
            }
        }
        __syncthreads();
        if (tid == 0) flags[blk * 32] = s + 1;
        if (tid < NBD) {
            while (flags[tid * 32] <= s) { }
        }
        __threadfence();
        __syncthreads();
    }
}

// ---------------- Kernel C: tag projection ----------------
__global__ __launch_bounds__(256) void tag_kernel(
    const float* __restrict__ w_tag, const float* __restrict__ b_tag)
{
    int t = blockIdx.x;
    __shared__ __align__(16) float row[2 * HDIM];
    int tid = threadIdx.x; // 256
    ((float4*)row)[tid] = ((const float4*)&g_lstm[t][0])[tid];
    __syncthreads();

    int lane8 = tid & 7;
    int k = tid >> 3;     // 0..31
    const float4* wr = (const float4*)(w_tag + (size_t)k * 2 * HDIM);
    const float4* r4 = (const float4*)row;
    float acc = 0.f;
#pragma unroll
    for (int i = 0; i < 32; i++) {
        float4 w = wr[lane8 + 8 * i];
        float4 x = r4[lane8 + 8 * i];
        acc = fmaf(w.x, x.x, acc);
        acc = fmaf(w.y, x.y, acc);
        acc = fmaf(w.z, x.z, acc);
        acc = fmaf(w.w, x.w, acc);
    }
    acc += __shfl_down_sync(0xffffffffu, acc, 4, 8);
    acc += __shfl_down_sync(0xffffffffu, acc, 2, 8);
    acc += __shfl_down_sync(0xffffffffu, acc, 1, 8);
    if (lane8 == 0) g_feats[t][k] = acc + b_tag[k];
}

// ---------------- Kernel D: Viterbi decode (one warp) ----------------
__global__ void viterbi_kernel(const float* __restrict__ trans,
                               float* __restrict__ out)
{
    __shared__ float fv[KTAG];
    __shared__ unsigned char bp[TT][KTAG];
    int tid = threadIdx.x;  // 32, thread = next-tag index

    float tr[KTAG];
#pragma unroll
    for (int p = 0; p < KTAG; p++) tr[p] = trans[tid * KTAG + p];
    float stoprow = trans[STOP_TAG * KTAG + tid];

    fv[tid] = (tid == START_TAG) ? 0.f : NEGV;
    __syncwarp();

    for (int t = 0; t < TT; t++) {
        float best = -3.4e38f;
        int bi = 0;
#pragma unroll
        for (int p = 0; p < KTAG; p++) {
            float sc = fv[p] + tr[p];
            if (sc > best) { best = sc; bi = p; }
        }
        bp[t][tid] = (unsigned char)bi;
        float nf = best + g_feats[t][tid];
        __syncwarp();
        fv[tid] = nf;
        __syncwarp();
    }

    float bv = fv[tid] + stoprow;
    int bidx = tid;
#pragma unroll
    for (int off = 16; off > 0; off >>= 1) {
        float ov = __shfl_down_sync(0xffffffffu, bv, off);
        int oi   = __shfl_down_sync(0xffffffffu, bidx, off);
        if (ov > bv || (ov == bv && oi < bidx)) { bv = ov; bidx = oi; }
    }
    bv   = __shfl_sync(0xffffffffu, bv, 0);
    bidx = __shfl_sync(0xffffffffu, bidx, 0);

    if (tid == 0) {
        out[0] = bv;                     // score
        out[TT] = (float)bidx;           // path[T-1] = best
        int tag = bidx;
        for (int t = TT - 1; t >= 1; t--) {
            tag = bp[t][tag];
            out[t] = (float)tag;         // path[t-1]
        }
    }
}

// ---------------- launch ----------------
extern "C" void kernel_launch(void* const* d_in, const int* in_sizes, int n_in,
                              void* d_out, int out_size)
{
    const int*   sentence = (const int*)d_in[0];
    const float* embed    = (const float*)d_in[1];
    const float* w_ih_f   = (const float*)d_in[2];
    const float* w_hh_f   = (const float*)d_in[3];
    const float* b_ih_f   = (const float*)d_in[4];
    const float* b_hh_f   = (const float*)d_in[5];
    const float* w_ih_b   = (const float*)d_in[6];
    const float* w_hh_b   = (const float*)d_in[7];
    const float* b_ih_b   = (const float*)d_in[8];
    const float* b_hh_b   = (const float*)d_in[9];
    const float* h0       = (const float*)d_in[10];
    const float* c0       = (const float*)d_in[11];
    const float* w_tag    = (const float*)d_in[12];
    const float* b_tag    = (const float*)d_in[13];
    const float* trans    = (const float*)d_in[14];
    float* out = (float*)d_out;

    reset_kernel<<<1, 128>>>();

    dim3 ggrid(G4 / 128, TT / 128, 2);   // 16 x 4 x 2 = 128 blocks
    gemm_xw_kernel<<<ggrid, 256>>>(sentence, embed,
                                   w_ih_f, b_ih_f, b_hh_f,
                                   w_ih_b, b_ih_b, b_hh_b);

    lstm_kernel<<<2 * NBD, LSTM_THREADS>>>(w_hh_f, w_hh_b, h0, c0);

    tag_kernel<<<TT, 256>>>(w_tag, b_tag);

    viterbi_kernel<<<1, 32>>>(trans, out);
}

// round 4
// speedup vs baseline: 1.2022x; 1.0684x over previous
#include <cuda_runtime.h>
#include <cstdint>

// Problem constants
#define TT   512      // sequence length
#define EE   1024     // embedding dim
#define HDIM 512      // per-direction hidden
#define G4   2048     // 4*HDIM gate rows
#define KTAG 32       // tags
#define NEGV (-10000.0f)
#define START_TAG 30
#define STOP_TAG  31

// LSTM recurrent kernel config
#define NBD  64              // blocks per direction
#define JPB  (HDIM / NBD)    // h-indices per block = 8
#define LSTM_THREADS 256

// ---------------- scratch (device globals; no allocation) ----------------
__device__ float g_xw[2][TT][G4];        // input projections + biases (scan-step indexed)
__device__ float g_lstm[TT][2 * HDIM];   // concatenated [hf | hb] (time indexed)
__device__ float g_feats[TT][KTAG];      // tag scores
__device__ int   g_flag[2][NBD * 32];    // per-writer step flags, 128B stride
__device__ float g_hx[2][2][NBD][32];    // h exchange, double-buffered, 128B/writer

// ---------------- memory-model helpers (no MEMBAR) ----------------
__device__ __forceinline__ int ldg_acquire(const int* p) {
    int v;
    asm volatile("ld.global.acquire.gpu.b32 %0, [%1];" : "=r"(v) : "l"(p) : "memory");
    return v;
}
__device__ __forceinline__ void stg_release(int* p, int v) {
    asm volatile("st.global.release.gpu.b32 [%0], %1;" :: "l"(p), "r"(v) : "memory");
}
__device__ __forceinline__ float4 ldg_relaxed_v4(const float4* p) {
    float4 v;
    asm volatile("ld.global.relaxed.gpu.v4.f32 {%0,%1,%2,%3}, [%4];"
                 : "=f"(v.x), "=f"(v.y), "=f"(v.z), "=f"(v.w) : "l"(p) : "memory");
    return v;
}
__device__ __forceinline__ void stg_relaxed_v4(float4* p, float4 v) {
    asm volatile("st.global.relaxed.gpu.v4.f32 [%0], {%1,%2,%3,%4};"
                 :: "l"(p), "f"(v.x), "f"(v.y), "f"(v.z), "f"(v.w) : "memory");
}

// ---------------- reset flags each launch ----------------
__global__ void reset_kernel() {
    int t = threadIdx.x;           // 128 threads
    if (t < 64)       g_flag[0][t * 32] = 0;
    else              g_flag[1][(t - 64) * 32] = 0;
}

// ---------------- Kernel A: embed-gather + input projection GEMM ---------
__global__ __launch_bounds__(256, 1) void gemm_xw_kernel(
    const int* __restrict__ sentence,
    const float* __restrict__ embed,
    const float* __restrict__ w_ih_f, const float* __restrict__ b_ih_f,
    const float* __restrict__ b_hh_f,
    const float* __restrict__ w_ih_b, const float* __restrict__ b_ih_b,
    const float* __restrict__ b_hh_b)
{
    int dir = blockIdx.z;
    const float* W  = dir ? w_ih_b : w_ih_f;
    const float* Bi = dir ? b_ih_b : b_ih_f;
    const float* Bh = dir ? b_hh_b : b_hh_f;

    int n0 = blockIdx.x * 128;   // gate-row tile
    int m0 = blockIdx.y * 128;   // scan-step tile

    __shared__ __align__(16) float As[8][128];
    __shared__ __align__(16) float Bs[8][128];

    int tid = threadIdx.x;
    int tx = tid & 15;           // 0..15 -> 8 output cols
    int ty = tid >> 4;           // 0..15 -> 8 output rows

    int lrow = tid >> 1;         // 0..127 load row
    int lq   = tid & 1;          // which float4 of the 8-wide k slab

    int sglob = m0 + lrow;                       // scan step
    int sidx  = dir ? (TT - 1 - sglob) : sglob;  // token consumed there
    const float* aptr = embed + (size_t)sentence[sidx] * EE + lq * 4;
    const float* bptr = W + (size_t)(n0 + lrow) * EE + lq * 4;

    float acc[8][8];
#pragma unroll
    for (int i = 0; i < 8; i++)
#pragma unroll
        for (int j = 0; j < 8; j++) acc[i][j] = 0.f;

    float4 a_nx = *(const float4*)aptr;
    float4 b_nx = *(const float4*)bptr;

    for (int k0 = 0; k0 < EE; k0 += 8) {
        As[lq * 4 + 0][lrow] = a_nx.x; As[lq * 4 + 1][lrow] = a_nx.y;
        As[lq * 4 + 2][lrow] = a_nx.z; As[lq * 4 + 3][lrow] = a_nx.w;
        Bs[lq * 4 + 0][lrow] = b_nx.x; Bs[lq * 4 + 1][lrow] = b_nx.y;
        Bs[lq * 4 + 2][lrow] = b_nx.z; Bs[lq * 4 + 3][lrow] = b_nx.w;
        __syncthreads();

        if (k0 + 8 < EE) {
            a_nx = *(const float4*)(aptr + k0 + 8);
            b_nx = *(const float4*)(bptr + k0 + 8);
        }

#pragma unroll
        for (int k = 0; k < 8; k++) {
            float4 a0 = ((const float4*)As[k])[ty * 2];
            float4 a1 = ((const float4*)As[k])[ty * 2 + 1];
            float4 b0 = ((const float4*)Bs[k])[tx * 2];
            float4 b1 = ((const float4*)Bs[k])[tx * 2 + 1];
            float a[8] = {a0.x, a0.y, a0.z, a0.w, a1.x, a1.y, a1.z, a1.w};
            float b[8] = {b0.x, b0.y, b0.z, b0.w, b1.x, b1.y, b1.z, b1.w};
#pragma unroll
            for (int i = 0; i < 8; i++)
#pragma unroll
                for (int j = 0; j < 8; j++)
                    acc[i][j] = fmaf(a[i], b[j], acc[i][j]);
        }
        __syncthreads();
    }

    int rbase = n0 + tx * 8;
    float4 bi0 = *(const float4*)(Bi + rbase);
    float4 bi1 = *(const float4*)(Bi + rbase + 4);
    float4 bh0 = *(const float4*)(Bh + rbase);
    float4 bh1 = *(const float4*)(Bh + rbase + 4);
    float bias[8] = {bi0.x + bh0.x, bi0.y + bh0.y, bi0.z + bh0.z, bi0.w + bh0.w,
                     bi1.x + bh1.x, bi1.y + bh1.y, bi1.z + bh1.z, bi1.w + bh1.w};
#pragma unroll
    for (int i = 0; i < 8; i++) {
        int m = m0 + ty * 8 + i;
        float4 o0 = make_float4(acc[i][0] + bias[0], acc[i][1] + bias[1],
                                acc[i][2] + bias[2], acc[i][3] + bias[3]);
        float4 o1 = make_float4(acc[i][4] + bias[4], acc[i][5] + bias[5],
                                acc[i][6] + bias[6], acc[i][7] + bias[7]);
        *(float4*)&g_xw[dir][m][rbase]     = o0;
        *(float4*)&g_xw[dir][m][rbase + 4] = o1;
    }
}

// ---------------- Kernel B: persistent recurrent LSTM --------------------
// 64 blocks/dir; weights in registers. Fenceless release/acquire exchange:
// writer lane0: 2x st.relaxed.v4 payload + st.release flag.
// readers: per-writer acquire-poll then immediate payload fetch (overlapped).
__global__ __launch_bounds__(LSTM_THREADS, 1) void lstm_kernel(
    const float* __restrict__ w_hh_f,
    const float* __restrict__ w_hh_b,
    const float* __restrict__ h0,
    const float* __restrict__ c0)
{
    __shared__ __align__(16) float hbuf[HDIM];
    __shared__ float gbuf[32];
    __shared__ __align__(16) float hvx[8];

    int bid = blockIdx.x;
    int dir = bid / NBD;
    int blk = bid % NBD;
    int j0  = blk * JPB;
    int tid = threadIdx.x;
    int lane8 = tid & 7;
    int task  = tid >> 3;        // 0..31 = gi*8 + jj
    int gi    = task >> 3;
    int jj    = task & 7;

    const float* w_hh = dir ? w_hh_b : w_hh_f;

    // Weights into registers
    const float4* wrow = (const float4*)(w_hh + (size_t)(gi * HDIM + j0 + jj) * HDIM);
    float4 w[16];
#pragma unroll
    for (int i = 0; i < 16; i++) w[i] = wrow[lane8 + 8 * i];

    float c_reg = (tid < JPB) ? c0[dir * HDIM + j0 + tid] : 0.f;

    int pw = tid >> 1;           // writer this thread tracks (tid<128)
    int pq = tid & 1;            // which float4 of that writer's payload
    const int* pflag = &g_flag[dir][pw * 32];
    int* myflag = &g_flag[dir][blk * 32];

    for (int s = 0; s < TT; s++) {
        int t = dir ? (TT - 1 - s) : s;

        if (s == 0) {
            if (tid < 128)
                ((float4*)hbuf)[tid] = ((const float4*)(h0 + dir * HDIM))[tid];
        } else if (tid < 128) {
            // acquire-poll writer pw, then fetch its 16B payload chunk
            while (ldg_acquire(pflag) < s) { }
            float4 hv4 = ldg_relaxed_v4(
                (const float4*)&g_hx[dir][(s - 1) & 1][pw][0] + pq);
            *((float4*)&hbuf[pw * 8] + pq) = hv4;
        }

        float xwv = 0.f;
        if (lane8 == 0) xwv = __ldcg(&g_xw[dir][s][gi * HDIM + j0 + jj]);
        __syncthreads();

        // h . w_row
        float acc = 0.f;
        const float4* h4 = (const float4*)hbuf;
#pragma unroll
        for (int i = 0; i < 16; i++) {
            float4 h = h4[lane8 + 8 * i];
            acc = fmaf(w[i].x, h.x, acc);
            acc = fmaf(w[i].y, h.y, acc);
            acc = fmaf(w[i].z, h.z, acc);
            acc = fmaf(w[i].w, h.w, acc);
        }
        acc += __shfl_down_sync(0xffffffffu, acc, 4, 8);
        acc += __shfl_down_sync(0xffffffffu, acc, 2, 8);
        acc += __shfl_down_sync(0xffffffffu, acc, 1, 8);
        if (lane8 == 0) gbuf[task] = acc + xwv;
        __syncthreads();

        // activations in warp 0: lane = gate*8 + jj
        if (tid < 32) {
            float gval = gbuf[tid];
            float act;
            if ((tid >> 3) == 2) act = tanhf(gval);                 // g gate
            else                 act = 1.f / (1.f + expf(-gval));   // i,f,o
            float xf = __shfl_sync(0xffffffffu, act, tid + 8);
            float xg = __shfl_sync(0xffffffffu, act, tid + 16);
            float xo = __shfl_sync(0xffffffffu, act, tid + 24);
            if (tid < JPB) {
                c_reg = fmaf(xf, c_reg, act * xg);   // act = sigmoid(i)
                float hv = xo * tanhf(c_reg);
                g_lstm[t][dir * HDIM + j0 + tid] = hv;  // for tag kernel
                hvx[tid] = hv;
            }
            __syncwarp();
            if (tid == 0) {
                float4 p0 = *(const float4*)&hvx[0];
                float4 p1 = *(const float4*)&hvx[4];
                float4* dst = (float4*)&g_hx[dir][s & 1][blk][0];
                stg_relaxed_v4(dst, p0);
                stg_relaxed_v4(dst + 1, p1);
                stg_release(myflag, s + 1);          // orders prior stores
            }
        }
        // No extra block barrier: every thread passes the post-reduce
        // __syncthreads() above before writing hbuf at step s+1, which
        // orders this step's hbuf reads before those writes.
    }
}

// ---------------- Kernel C: tag projection ----------------
__global__ __launch_bounds__(256) void tag_kernel(
    const float* __restrict__ w_tag, const float* __restrict__ b_tag)
{
    int t = blockIdx.x;
    __shared__ __align__(16) float row[2 * HDIM];
    int tid = threadIdx.x; // 256
    ((float4*)row)[tid] = ((const float4*)&g_lstm[t][0])[tid];
    __syncthreads();

    int lane8 = tid & 7;
    int k = tid >> 3;     // 0..31
    const float4* wr = (const float4*)(w_tag + (size_t)k * 2 * HDIM);
    const float4* r4 = (const float4*)row;
    float acc = 0.f;
#pragma unroll
    for (int i = 0; i < 32; i++) {
        float4 w = wr[lane8 + 8 * i];
        float4 x = r4[lane8 + 8 * i];
        acc = fmaf(w.x, x.x, acc);
        acc = fmaf(w.y, x.y, acc);
        acc = fmaf(w.z, x.z, acc);
        acc = fmaf(w.w, x.w, acc);
    }
    acc += __shfl_down_sync(0xffffffffu, acc, 4, 8);
    acc += __shfl_down_sync(0xffffffffu, acc, 2, 8);
    acc += __shfl_down_sync(0xffffffffu, acc, 1, 8);
    if (lane8 == 0) g_feats[t][k] = acc + b_tag[k];
}

// ---------------- Kernel D: Viterbi decode (one warp) ----------------
__global__ void viterbi_kernel(const float* __restrict__ trans,
                               float* __restrict__ out)
{
    __shared__ float fv[KTAG];
    __shared__ unsigned char bp[TT][KTAG];
    int tid = threadIdx.x;  // 32, thread = next-tag index

    float tr[KTAG];
#pragma unroll
    for (int p = 0; p < KTAG; p++) tr[p] = trans[tid * KTAG + p];
    float stoprow = trans[STOP_TAG * KTAG + tid];

    fv[tid] = (tid == START_TAG) ? 0.f : NEGV;
    __syncwarp();

    for (int t = 0; t < TT; t++) {
        float best = -3.4e38f;
        int bi = 0;
#pragma unroll
        for (int p = 0; p < KTAG; p++) {
            float sc = fv[p] + tr[p];
            if (sc > best) { best = sc; bi = p; }
        }
        bp[t][tid] = (unsigned char)bi;
        float nf = best + g_feats[t][tid];
        __syncwarp();
        fv[tid] = nf;
        __syncwarp();
    }

    float bv = fv[tid] + stoprow;
    int bidx = tid;
#pragma unroll
    for (int off = 16; off > 0; off >>= 1) {
        float ov = __shfl_down_sync(0xffffffffu, bv, off);
        int oi   = __shfl_down_sync(0xffffffffu, bidx, off);
        if (ov > bv || (ov == bv && oi < bidx)) { bv = ov; bidx = oi; }
    }
    bv   = __shfl_sync(0xffffffffu, bv, 0);
    bidx = __shfl_sync(0xffffffffu, bidx, 0);

    if (tid == 0) {
        out[0] = bv;                     // score
        out[TT] = (float)bidx;           // path[T-1] = best
        int tag = bidx;
        for (int t = TT - 1; t >= 1; t--) {
            tag = bp[t][tag];
            out[t] = (float)tag;         // path[t-1]
        }
    }
}

// ---------------- launch ----------------
extern "C" void kernel_launch(void* const* d_in, const int* in_sizes, int n_in,
                              void* d_out, int out_size)
{
    const int*   sentence = (const int*)d_in[0];
    const float* embed    = (const float*)d_in[1];
    const float* w_ih_f   = (const float*)d_in[2];
    const float* w_hh_f   = (const float*)d_in[3];
    const float* b_ih_f   = (const float*)d_in[4];
    const float* b_hh_f   = (const float*)d_in[5];
    const float* w_ih_b   = (const float*)d_in[6];
    const float* w_hh_b   = (const float*)d_in[7];
    const float* b_ih_b   = (const float*)d_in[8];
    const float* b_hh_b   = (const float*)d_in[9];
    const float* h0       = (const float*)d_in[10];
    const float* c0       = (const float*)d_in[11];
    const float* w_tag    = (const float*)d_in[12];
    const float* b_tag    = (const float*)d_in[13];
    const float* trans    = (const float*)d_in[14];
    float* out = (float*)d_out;

    reset_kernel<<<1, 128>>>();

    dim3 ggrid(G4 / 128, TT / 128, 2);   // 16 x 4 x 2 = 128 blocks
    gemm_xw_kernel<<<ggrid, 256>>>(sentence, embed,
                                   w_ih_f, b_ih_f, b_hh_f,
                                   w_ih_b, b_ih_b, b_hh_b);

    lstm_kernel<<<2 * NBD, LSTM_THREADS>>>(w_hh_f, w_hh_b, h0, c0);

    tag_kernel<<<TT, 256>>>(w_tag, b_tag);

    viterbi_kernel<<<1, 32>>>(trans, out);
}

// round 5
// speedup vs baseline: 2.1308x; 1.7723x over previous
#include <cuda_runtime.h>
#include <cstdint>

// Problem constants
#define TT   512      // sequence length
#define EE   1024     // embedding dim
#define HDIM 512      // per-direction hidden
#define G4   2048     // 4*HDIM gate rows
#define KTAG 32       // tags
#define NEGV (-10000.0f)
#define START_TAG 30
#define STOP_TAG  31

// LSTM recurrent kernel config
#define NBD  64              // blocks per direction
#define JPB  (HDIM / NBD)    // h-indices per block = 8
#define LSTM_THREADS 256
#define SENT 0x7FC00001u     // NaN sentinel: h = sigmoid*tanh can never be NaN

// ---------------- scratch (device globals; no allocation) ----------------
__device__ float g_xw[2][TT][G4];          // input projections + biases (scan-step indexed)
__device__ float g_lstm[TT][2 * HDIM];     // concatenated [hf | hb] (time indexed)
__device__ float g_feats[TT][KTAG];        // tag scores
__device__ float g_hx[2][TT][NBD][JPB];    // per-step h exchange slots (2 MB)

// ---------------- memory-model helpers ----------------
__device__ __forceinline__ float4 ldg_relaxed_v4(const float4* p) {
    float4 v;
    asm volatile("ld.global.relaxed.gpu.v4.f32 {%0,%1,%2,%3}, [%4];"
                 : "=f"(v.x), "=f"(v.y), "=f"(v.z), "=f"(v.w) : "l"(p) : "memory");
    return v;
}
__device__ __forceinline__ void stg_relaxed_v4(float4* p, float4 v) {
    asm volatile("st.global.relaxed.gpu.v4.f32 [%0], {%1,%2,%3,%4};"
                 :: "l"(p), "f"(v.x), "f"(v.y), "f"(v.z), "f"(v.w) : "memory");
}
__device__ __forceinline__ bool has_sent(float4 v) {
    return (__float_as_uint(v.x) == SENT) | (__float_as_uint(v.y) == SENT) |
           (__float_as_uint(v.z) == SENT) | (__float_as_uint(v.w) == SENT);
}

// ---------------- poison the exchange slots each launch ----------------
__global__ __launch_bounds__(256) void poison_kernel() {
    // g_hx = 2*512*64*8 floats = 131072 float4
    float4* p = (float4*)g_hx;
    uint32_t s = SENT;
    float4 v = make_float4(__uint_as_float(s), __uint_as_float(s),
                           __uint_as_float(s), __uint_as_float(s));
    p[blockIdx.x * 256 + threadIdx.x] = v;
}

// ---------------- Kernel A: embed-gather + input projection GEMM ---------
__global__ __launch_bounds__(256, 1) void gemm_xw_kernel(
    const int* __restrict__ sentence,
    const float* __restrict__ embed,
    const float* __restrict__ w_ih_f, const float* __restrict__ b_ih_f,
    const float* __restrict__ b_hh_f,
    const float* __restrict__ w_ih_b, const float* __restrict__ b_ih_b,
    const float* __restrict__ b_hh_b)
{
    int dir = blockIdx.z;
    const float* W  = dir ? w_ih_b : w_ih_f;
    const float* Bi = dir ? b_ih_b : b_ih_f;
    const float* Bh = dir ? b_hh_b : b_hh_f;

    int n0 = blockIdx.x * 128;   // gate-row tile
    int m0 = blockIdx.y * 128;   // scan-step tile

    __shared__ __align__(16) float As[8][128];
    __shared__ __align__(16) float Bs[8][128];

    int tid = threadIdx.x;
    int tx = tid & 15;           // 0..15 -> 8 output cols
    int ty = tid >> 4;           // 0..15 -> 8 output rows

    int lrow = tid >> 1;         // 0..127 load row
    int lq   = tid & 1;          // which float4 of the 8-wide k slab

    int sglob = m0 + lrow;                       // scan step
    int sidx  = dir ? (TT - 1 - sglob) : sglob;  // token consumed there
    const float* aptr = embed + (size_t)sentence[sidx] * EE + lq * 4;
    const float* bptr = W + (size_t)(n0 + lrow) * EE + lq * 4;

    float acc[8][8];
#pragma unroll
    for (int i = 0; i < 8; i++)
#pragma unroll
        for (int j = 0; j < 8; j++) acc[i][j] = 0.f;

    float4 a_nx = *(const float4*)aptr;
    float4 b_nx = *(const float4*)bptr;

    for (int k0 = 0; k0 < EE; k0 += 8) {
        As[lq * 4 + 0][lrow] = a_nx.x; As[lq * 4 + 1][lrow] = a_nx.y;
        As[lq * 4 + 2][lrow] = a_nx.z; As[lq * 4 + 3][lrow] = a_nx.w;
        Bs[lq * 4 + 0][lrow] = b_nx.x; Bs[lq * 4 + 1][lrow] = b_nx.y;
        Bs[lq * 4 + 2][lrow] = b_nx.z; Bs[lq * 4 + 3][lrow] = b_nx.w;
        __syncthreads();

        if (k0 + 8 < EE) {
            a_nx = *(const float4*)(aptr + k0 + 8);
            b_nx = *(const float4*)(bptr + k0 + 8);
        }

#pragma unroll
        for (int k = 0; k < 8; k++) {
            float4 a0 = ((const float4*)As[k])[ty * 2];
            float4 a1 = ((const float4*)As[k])[ty * 2 + 1];
            float4 b0 = ((const float4*)Bs[k])[tx * 2];
            float4 b1 = ((const float4*)Bs[k])[tx * 2 + 1];
            float a[8] = {a0.x, a0.y, a0.z, a0.w, a1.x, a1.y, a1.z, a1.w};
            float b[8] = {b0.x, b0.y, b0.z, b0.w, b1.x, b1.y, b1.z, b1.w};
#pragma unroll
            for (int i = 0; i < 8; i++)
#pragma unroll
                for (int j = 0; j < 8; j++)
                    acc[i][j] = fmaf(a[i], b[j], acc[i][j]);
        }
        __syncthreads();
    }

    int rbase = n0 + tx * 8;
    float4 bi0 = *(const float4*)(Bi + rbase);
    float4 bi1 = *(const float4*)(Bi + rbase + 4);
    float4 bh0 = *(const float4*)(Bh + rbase);
    float4 bh1 = *(const float4*)(Bh + rbase + 4);
    float bias[8] = {bi0.x + bh0.x, bi0.y + bh0.y, bi0.z + bh0.z, bi0.w + bh0.w,
                     bi1.x + bh1.x, bi1.y + bh1.y, bi1.z + bh1.z, bi1.w + bh1.w};
#pragma unroll
    for (int i = 0; i < 8; i++) {
        int m = m0 + ty * 8 + i;
        float4 o0 = make_float4(acc[i][0] + bias[0], acc[i][1] + bias[1],
                                acc[i][2] + bias[2], acc[i][3] + bias[3]);
        float4 o1 = make_float4(acc[i][4] + bias[4], acc[i][5] + bias[5],
                                acc[i][6] + bias[6], acc[i][7] + bias[7]);
        *(float4*)&g_xw[dir][m][rbase]     = o0;
        *(float4*)&g_xw[dir][m][rbase + 4] = o1;
    }
}

// ---------------- Kernel B: persistent recurrent LSTM --------------------
// Data-is-the-flag exchange: per-step poisoned slots; readers poll the
// payload itself (one L2 trip), writers do two relaxed 16B stores. No
// flags, no fences, no acquire chains.
__global__ __launch_bounds__(LSTM_THREADS, 1) void lstm_kernel(
    const float* __restrict__ w_hh_f,
    const float* __restrict__ w_hh_b,
    const float* __restrict__ h0,
    const float* __restrict__ c0)
{
    __shared__ __align__(16) float hbuf[HDIM];
    __shared__ float gbuf[32];
    __shared__ __align__(16) float hvx[8];

    int bid = blockIdx.x;
    int dir = bid / NBD;
    int blk = bid % NBD;
    int j0  = blk * JPB;
    int tid = threadIdx.x;
    int lane8 = tid & 7;
    int task  = tid >> 3;        // 0..31 = gi*8 + jj
    int gi    = task >> 3;
    int jj    = task & 7;

    const float* w_hh = dir ? w_hh_b : w_hh_f;

    // Weights into registers
    const float4* wrow = (const float4*)(w_hh + (size_t)(gi * HDIM + j0 + jj) * HDIM);
    float4 w[16];
#pragma unroll
    for (int i = 0; i < 16; i++) w[i] = wrow[lane8 + 8 * i];

    float c_reg = (tid < JPB) ? c0[dir * HDIM + j0 + tid] : 0.f;

    int pw = tid >> 1;           // writer block this thread tracks (tid<128)
    int pq = tid & 1;            // which 16B chunk of that writer's payload
    const float* xwbase = &g_xw[dir][0][gi * HDIM + j0 + jj];

    for (int s = 0; s < TT; s++) {
        int t = dir ? (TT - 1 - s) : s;

        // prefetch xw before the spin so its latency hides under the poll
        float xwv = 0.f;
        if (lane8 == 0) xwv = __ldcg(xwbase + (size_t)s * G4);

        if (s == 0) {
            if (tid < 128)
                ((float4*)hbuf)[tid] = ((const float4*)(h0 + dir * HDIM))[tid];
        } else if (tid < 128) {
            const float4* src = (const float4*)&g_hx[dir][s - 1][pw][0] + pq;
            float4 hv4;
            do { hv4 = ldg_relaxed_v4(src); } while (has_sent(hv4));
            *((float4*)&hbuf[pw * 8] + pq) = hv4;
        }
        __syncthreads();

        // h . w_row
        float acc = 0.f;
        const float4* h4 = (const float4*)hbuf;
#pragma unroll
        for (int i = 0; i < 16; i++) {
            float4 h = h4[lane8 + 8 * i];
            acc = fmaf(w[i].x, h.x, acc);
            acc = fmaf(w[i].y, h.y, acc);
            acc = fmaf(w[i].z, h.z, acc);
            acc = fmaf(w[i].w, h.w, acc);
        }
        acc += __shfl_down_sync(0xffffffffu, acc, 4, 8);
        acc += __shfl_down_sync(0xffffffffu, acc, 2, 8);
        acc += __shfl_down_sync(0xffffffffu, acc, 1, 8);
        if (lane8 == 0) gbuf[task] = acc + xwv;
        __syncthreads();

        // activations in warp 0: lane = gate*8 + jj
        if (tid < 32) {
            float gval = gbuf[tid];
            float act;
            if ((tid >> 3) == 2) act = tanhf(gval);                 // g gate
            else                 act = 1.f / (1.f + expf(-gval));   // i,f,o
            float xf = __shfl_sync(0xffffffffu, act, tid + 8);
            float xg = __shfl_sync(0xffffffffu, act, tid + 16);
            float xo = __shfl_sync(0xffffffffu, act, tid + 24);
            if (tid < JPB) {
                c_reg = fmaf(xf, c_reg, act * xg);   // act = sigmoid(i)
                float hv = xo * tanhf(c_reg);
                g_lstm[t][dir * HDIM + j0 + tid] = hv;  // for tag kernel
                hvx[tid] = hv;
            }
            __syncwarp();
            if (tid < 2) {
                float4 p = *((const float4*)&hvx[0] + tid);
                stg_relaxed_v4((float4*)&g_hx[dir][s][blk][0] + tid, p);
            }
        }
        // No end-of-step barrier needed: the post-reduce __syncthreads
        // orders this step's hbuf reads before next step's hbuf writes.
    }
}

// ---------------- Kernel C: tag projection ----------------
__global__ __launch_bounds__(256) void tag_kernel(
    const float* __restrict__ w_tag, const float* __restrict__ b_tag)
{
    int t = blockIdx.x;
    __shared__ __align__(16) float row[2 * HDIM];
    int tid = threadIdx.x; // 256
    ((float4*)row)[tid] = ((const float4*)&g_lstm[t][0])[tid];
    __syncthreads();

    int lane8 = tid & 7;
    int k = tid >> 3;     // 0..31
    const float4* wr = (const float4*)(w_tag + (size_t)k * 2 * HDIM);
    const float4* r4 = (const float4*)row;
    float acc = 0.f;
#pragma unroll
    for (int i = 0; i < 32; i++) {
        float4 w = wr[lane8 + 8 * i];
        float4 x = r4[lane8 + 8 * i];
        acc = fmaf(w.x, x.x, acc);
        acc = fmaf(w.y, x.y, acc);
        acc = fmaf(w.z, x.z, acc);
        acc = fmaf(w.w, x.w, acc);
    }
    acc += __shfl_down_sync(0xffffffffu, acc, 4, 8);
    acc += __shfl_down_sync(0xffffffffu, acc, 2, 8);
    acc += __shfl_down_sync(0xffffffffu, acc, 1, 8);
    if (lane8 == 0) g_feats[t][k] = acc + b_tag[k];
}

// ---------------- Kernel D: Viterbi decode (one warp) ----------------
__global__ void viterbi_kernel(const float* __restrict__ trans,
                               float* __restrict__ out)
{
    __shared__ float fv[KTAG];
    __shared__ unsigned char bp[TT][KTAG];
    int tid = threadIdx.x;  // 32, thread = next-tag index

    float tr[KTAG];
#pragma unroll
    for (int p = 0; p < KTAG; p++) tr[p] = trans[tid * KTAG + p];
    float stoprow = trans[STOP_TAG * KTAG + tid];

    fv[tid] = (tid == START_TAG) ? 0.f : NEGV;
    __syncwarp();

    for (int t = 0; t < TT; t++) {
        float best = -3.4e38f;
        int bi = 0;
#pragma unroll
        for (int p = 0; p < KTAG; p++) {
            float sc = fv[p] + tr[p];
            if (sc > best) { best = sc; bi = p; }
        }
        bp[t][tid] = (unsigned char)bi;
        float nf = best + g_feats[t][tid];
        __syncwarp();
        fv[tid] = nf;
        __syncwarp();
    }

    float bv = fv[tid] + stoprow;
    int bidx = tid;
#pragma unroll
    for (int off = 16; off > 0; off >>= 1) {
        float ov = __shfl_down_sync(0xffffffffu, bv, off);
        int oi   = __shfl_down_sync(0xffffffffu, bidx, off);
        if (ov > bv || (ov == bv && oi < bidx)) { bv = ov; bidx = oi; }
    }
    bv   = __shfl_sync(0xffffffffu, bv, 0);
    bidx = __shfl_sync(0xffffffffu, bidx, 0);

    if (tid == 0) {
        out[0] = bv;                     // score
        out[TT] = (float)bidx;           // path[T-1] = best
        int tag = bidx;
        for (int t = TT - 1; t >= 1; t--) {
            tag = bp[t][tag];
            out[t] = (float)tag;         // path[t-1]
        }
    }
}

// ---------------- launch ----------------
extern "C" void kernel_launch(void* const* d_in, const int* in_sizes, int n_in,
                              void* d_out, int out_size)
{
    const int*   sentence = (const int*)d_in[0];
    const float* embed    = (const float*)d_in[1];
    const float* w_ih_f   = (const float*)d_in[2];
    const float* w_hh_f   = (const float*)d_in[3];
    const float* b_ih_f   = (const float*)d_in[4];
    const float* b_hh_f   = (const float*)d_in[5];
    const float* w_ih_b   = (const float*)d_in[6];
    const float* w_hh_b   = (const float*)d_in[7];
    const float* b_ih_b   = (const float*)d_in[8];
    const float* b_hh_b   = (const float*)d_in[9];
    const float* h0       = (const float*)d_in[10];
    const float* c0       = (const float*)d_in[11];
    const float* w_tag    = (const float*)d_in[12];
    const float* b_tag    = (const float*)d_in[13];
    const float* trans    = (const float*)d_in[14];
    float* out = (float*)d_out;

    // poison exchange slots: 131072 float4 / 256 = 512 blocks
    poison_kernel<<<512, 256>>>();

    dim3 ggrid(G4 / 128, TT / 128, 2);   // 16 x 4 x 2 = 128 blocks
    gemm_xw_kernel<<<ggrid, 256>>>(sentence, embed,
                                   w_ih_f, b_ih_f, b_hh_f,
                                   w_ih_b, b_ih_b, b_hh_b);

    lstm_kernel<<<2 * NBD, LSTM_THREADS>>>(w_hh_f, w_hh_b, h0, c0);

    tag_kernel<<<TT, 256>>>(w_tag, b_tag);

    viterbi_kernel<<<1, 32>>>(trans, out);
}

// round 6
// speedup vs baseline: 2.2106x; 1.0375x over previous
#include <cuda_runtime.h>
#include <cstdint>

// Problem constants
#define TT   512      // sequence length
#define EE   1024     // embedding dim
#define HDIM 512      // per-direction hidden
#define G4   2048     // 4*HDIM gate rows
#define KTAG 32       // tags
#define NEGV (-10000.0f)
#define START_TAG 30
#define STOP_TAG  31

// LSTM recurrent kernel config
#define NBD  64              // blocks per direction
#define JPB  (HDIM / NBD)    // h-indices per block = 8
#define LSTM_THREADS 256
#define SENT 0x7FC00001u     // NaN sentinel: h = sigmoid*tanh can never be NaN

// ---------------- scratch (device globals; no allocation) ----------------
__device__ float g_xw[2][TT][G4];          // input projections + biases (scan-step indexed)
__device__ float g_lstm[TT][2 * HDIM];     // concatenated [hf | hb] (time indexed)
__device__ float g_feats[TT][KTAG];        // tag scores
__device__ float g_hx[2][TT][NBD][JPB];    // per-step h exchange slots (2 MB)

// ---------------- asm helpers ----------------
__device__ __forceinline__ float4 ldg_relaxed_v4(const float4* p) {
    float4 v;
    asm volatile("ld.global.relaxed.gpu.v4.f32 {%0,%1,%2,%3}, [%4];"
                 : "=f"(v.x), "=f"(v.y), "=f"(v.z), "=f"(v.w) : "l"(p) : "memory");
    return v;
}
__device__ __forceinline__ void stg_relaxed_v4(float4* p, float4 v) {
    asm volatile("st.global.relaxed.gpu.v4.f32 [%0], {%1,%2,%3,%4};"
                 :: "l"(p), "f"(v.x), "f"(v.y), "f"(v.z), "f"(v.w) : "memory");
}
__device__ __forceinline__ bool has_sent(float4 v) {
    return (__float_as_uint(v.x) == SENT) | (__float_as_uint(v.y) == SENT) |
           (__float_as_uint(v.z) == SENT) | (__float_as_uint(v.w) == SENT);
}
// packed f32x2 FMA (sm_100+; ptxas never emits this from C++)
__device__ __forceinline__ void fma2(uint64_t& d, uint64_t a, uint64_t b) {
    asm("fma.rn.f32x2 %0, %1, %2, %0;" : "+l"(d) : "l"(a), "l"(b));
}
__device__ __forceinline__ uint64_t pack2(float x, float y) {
    uint64_t r; asm("mov.b64 %0, {%1,%2};" : "=l"(r) : "f"(x), "f"(y)); return r;
}
__device__ __forceinline__ float2 unpack2(uint64_t v) {
    float2 f; asm("mov.b64 {%0,%1}, %2;" : "=f"(f.x), "=f"(f.y) : "l"(v)); return f;
}
__device__ __forceinline__ void lds_v2_u64(uint32_t addr, uint64_t& x, uint64_t& y) {
    asm volatile("ld.shared.v2.b64 {%0,%1}, [%2];" : "=l"(x), "=l"(y) : "r"(addr));
}
// fast activations: MUFU-based, rel err ~1e-6 (safe vs argmax margins)
__device__ __forceinline__ float fast_sig(float x) {
    return __fdividef(1.f, 1.f + __expf(-x));
}
__device__ __forceinline__ float fast_tanh(float x) {
    return 1.f - __fdividef(2.f, __expf(2.f * x) + 1.f);
}

// ---------------- poison the exchange slots each launch ----------------
__global__ __launch_bounds__(256) void poison_kernel() {
    // g_hx = 2*512*64*8 floats = 131072 float4
    float4* p = (float4*)g_hx;
    uint32_t s = SENT;
    float4 v = make_float4(__uint_as_float(s), __uint_as_float(s),
                           __uint_as_float(s), __uint_as_float(s));
    p[blockIdx.x * 256 + threadIdx.x] = v;
}

// ---------------- Kernel A: embed-gather + input projection GEMM ---------
// 128x128 tile, 8x8 per thread, packed f32x2 FMA inner loop.
__global__ __launch_bounds__(256, 1) void gemm_xw_kernel(
    const int* __restrict__ sentence,
    const float* __restrict__ embed,
    const float* __restrict__ w_ih_f, const float* __restrict__ b_ih_f,
    const float* __restrict__ b_hh_f,
    const float* __restrict__ w_ih_b, const float* __restrict__ b_ih_b,
    const float* __restrict__ b_hh_b)
{
    int dir = blockIdx.z;
    const float* W  = dir ? w_ih_b : w_ih_f;
    const float* Bi = dir ? b_ih_b : b_ih_f;
    const float* Bh = dir ? b_hh_b : b_hh_f;

    int n0 = blockIdx.x * 128;   // gate-row tile
    int m0 = blockIdx.y * 128;   // scan-step tile

    __shared__ __align__(16) float As[8][128];
    __shared__ __align__(16) float Bs[8][128];

    int tid = threadIdx.x;
    int tx = tid & 15;           // 0..15 -> 8 output cols
    int ty = tid >> 4;           // 0..15 -> 8 output rows

    int lrow = tid >> 1;         // 0..127 load row
    int lq   = tid & 1;          // which float4 of the 8-wide k slab

    int sglob = m0 + lrow;                       // scan step
    int sidx  = dir ? (TT - 1 - sglob) : sglob;  // token consumed there
    const float* aptr = embed + (size_t)sentence[sidx] * EE + lq * 4;
    const float* bptr = W + (size_t)(n0 + lrow) * EE + lq * 4;

    uint64_t acc2[8][4];
#pragma unroll
    for (int i = 0; i < 8; i++)
#pragma unroll
        for (int j = 0; j < 4; j++) acc2[i][j] = 0ull;

    uint32_t bs_base = (uint32_t)__cvta_generic_to_shared(&Bs[0][tx * 8]);
    uint32_t as_base = (uint32_t)__cvta_generic_to_shared(&As[0][ty * 8]);

    float4 a_nx = *(const float4*)aptr;
    float4 b_nx = *(const float4*)bptr;

    for (int k0 = 0; k0 < EE; k0 += 8) {
        As[lq * 4 + 0][lrow] = a_nx.x; As[lq * 4 + 1][lrow] = a_nx.y;
        As[lq * 4 + 2][lrow] = a_nx.z; As[lq * 4 + 3][lrow] = a_nx.w;
        Bs[lq * 4 + 0][lrow] = b_nx.x; Bs[lq * 4 + 1][lrow] = b_nx.y;
        Bs[lq * 4 + 2][lrow] = b_nx.z; Bs[lq * 4 + 3][lrow] = b_nx.w;
        __syncthreads();

        if (k0 + 8 < EE) {
            a_nx = *(const float4*)(aptr + k0 + 8);
            b_nx = *(const float4*)(bptr + k0 + 8);
        }

#pragma unroll
        for (int k = 0; k < 8; k++) {
            uint64_t a01, a23, a45, a67;
            lds_v2_u64(as_base + k * 512,      a01, a23);
            lds_v2_u64(as_base + k * 512 + 16, a45, a67);
            uint64_t b01, b23, b45, b67;
            lds_v2_u64(bs_base + k * 512,      b01, b23);
            lds_v2_u64(bs_base + k * 512 + 16, b45, b67);
            float2 a0 = unpack2(a01), a1 = unpack2(a23);
            float2 a2 = unpack2(a45), a3 = unpack2(a67);
            float a[8] = {a0.x, a0.y, a1.x, a1.y, a2.x, a2.y, a3.x, a3.y};
#pragma unroll
            for (int i = 0; i < 8; i++) {
                uint64_t aa = pack2(a[i], a[i]);
                fma2(acc2[i][0], aa, b01);
                fma2(acc2[i][1], aa, b23);
                fma2(acc2[i][2], aa, b45);
                fma2(acc2[i][3], aa, b67);
            }
        }
        __syncthreads();
    }

    int rbase = n0 + tx * 8;
    float4 bi0 = *(const float4*)(Bi + rbase);
    float4 bi1 = *(const float4*)(Bi + rbase + 4);
    float4 bh0 = *(const float4*)(Bh + rbase);
    float4 bh1 = *(const float4*)(Bh + rbase + 4);
    float bias[8] = {bi0.x + bh0.x, bi0.y + bh0.y, bi0.z + bh0.z, bi0.w + bh0.w,
                     bi1.x + bh1.x, bi1.y + bh1.y, bi1.z + bh1.z, bi1.w + bh1.w};
#pragma unroll
    for (int i = 0; i < 8; i++) {
        int m = m0 + ty * 8 + i;
        float2 p0 = unpack2(acc2[i][0]);
        float2 p1 = unpack2(acc2[i][1]);
        float2 p2 = unpack2(acc2[i][2]);
        float2 p3 = unpack2(acc2[i][3]);
        float4 o0 = make_float4(p0.x + bias[0], p0.y + bias[1],
                                p1.x + bias[2], p1.y + bias[3]);
        float4 o1 = make_float4(p2.x + bias[4], p2.y + bias[5],
                                p3.x + bias[6], p3.y + bias[7]);
        *(float4*)&g_xw[dir][m][rbase]     = o0;
        *(float4*)&g_xw[dir][m][rbase + 4] = o1;
    }
}

// ---------------- Kernel B: persistent recurrent LSTM --------------------
// Data-is-the-flag exchange + packed f32x2 dot + MUFU activations.
__global__ __launch_bounds__(LSTM_THREADS, 1) void lstm_kernel(
    const float* __restrict__ w_hh_f,
    const float* __restrict__ w_hh_b,
    const float* __restrict__ h0,
    const float* __restrict__ c0)
{
    __shared__ __align__(16) float hbuf[HDIM];
    __shared__ float gbuf[32];
    __shared__ __align__(16) float hvx[8];

    int bid = blockIdx.x;
    int dir = bid / NBD;
    int blk = bid % NBD;
    int j0  = blk * JPB;
    int tid = threadIdx.x;
    int lane8 = tid & 7;
    int task  = tid >> 3;        // 0..31 = gi*8 + jj
    int gi    = task >> 3;
    int jj    = task & 7;

    const float* w_hh = dir ? w_hh_b : w_hh_f;

    // Weights into registers as packed f32x2 pairs
    const float4* wrow = (const float4*)(w_hh + (size_t)(gi * HDIM + j0 + jj) * HDIM);
    uint64_t wp[32];
#pragma unroll
    for (int i = 0; i < 16; i++) {
        float4 w4 = wrow[lane8 + 8 * i];
        wp[2 * i]     = pack2(w4.x, w4.y);
        wp[2 * i + 1] = pack2(w4.z, w4.w);
    }

    float c_reg = (tid < JPB) ? c0[dir * HDIM + j0 + tid] : 0.f;

    int pw = tid >> 1;           // writer block this thread tracks (tid<128)
    int pq = tid & 1;            // which 16B chunk of that writer's payload
    const float* xwbase = &g_xw[dir][0][gi * HDIM + j0 + jj];
    uint32_t h_base = (uint32_t)__cvta_generic_to_shared(&hbuf[0]) + lane8 * 16;

    for (int s = 0; s < TT; s++) {
        int t = dir ? (TT - 1 - s) : s;

        // prefetch xw before the spin so its latency hides under the poll
        float xwv = 0.f;
        if (lane8 == 0) xwv = __ldcg(xwbase + (size_t)s * G4);

        if (s == 0) {
            if (tid < 128)
                ((float4*)hbuf)[tid] = ((const float4*)(h0 + dir * HDIM))[tid];
        } else if (tid < 128) {
            const float4* src = (const float4*)&g_hx[dir][s - 1][pw][0] + pq;
            float4 hv4;
            do { hv4 = ldg_relaxed_v4(src); } while (has_sent(hv4));
            *((float4*)&hbuf[pw * 8] + pq) = hv4;
        }
        __syncthreads();

        // h . w_row with packed f32x2 FMA, 4 independent chains
        uint64_t aA = 0ull, aB = 0ull, aC = 0ull, aD = 0ull;
#pragma unroll
        for (int i = 0; i < 16; i += 2) {
            uint64_t h0p, h1p, h2p, h3p;
            lds_v2_u64(h_base + i * 128, h0p, h1p);
            lds_v2_u64(h_base + i * 128 + 128, h2p, h3p);
            fma2(aA, wp[2 * i],     h0p);
            fma2(aB, wp[2 * i + 1], h1p);
            fma2(aC, wp[2 * i + 2], h2p);
            fma2(aD, wp[2 * i + 3], h3p);
        }
        float2 fA = unpack2(aA), fB = unpack2(aB);
        float2 fC = unpack2(aC), fD = unpack2(aD);
        float acc = ((fA.x + fA.y) + (fB.x + fB.y)) +
                    ((fC.x + fC.y) + (fD.x + fD.y));
        acc += __shfl_down_sync(0xffffffffu, acc, 4, 8);
        acc += __shfl_down_sync(0xffffffffu, acc, 2, 8);
        acc += __shfl_down_sync(0xffffffffu, acc, 1, 8);
        if (lane8 == 0) gbuf[task] = acc + xwv;
        __syncthreads();

        // activations in warp 0: lane = gate*8 + jj
        if (tid < 32) {
            float gval = gbuf[tid];
            float act;
            if ((tid >> 3) == 2) act = fast_tanh(gval);   // g gate
            else                 act = fast_sig(gval);    // i,f,o
            float xf = __shfl_sync(0xffffffffu, act, tid + 8);
            float xg = __shfl_sync(0xffffffffu, act, tid + 16);
            float xo = __shfl_sync(0xffffffffu, act, tid + 24);
            float hv = 0.f;
            if (tid < JPB) {
                c_reg = fmaf(xf, c_reg, act * xg);   // act = sigmoid(i)
                hv = xo * fast_tanh(c_reg);
                hvx[tid] = hv;
            }
            __syncwarp();
            if (tid < 2) {   // exchange store FIRST (critical path)
                float4 p = *((const float4*)&hvx[0] + tid);
                stg_relaxed_v4((float4*)&g_hx[dir][s][blk][0] + tid, p);
            }
            if (tid < JPB)
                g_lstm[t][dir * HDIM + j0 + tid] = hv;  // for tag kernel (off-path)
        }
        // The post-reduce __syncthreads orders this step's hbuf reads
        // before next step's hbuf writes.
    }
}

// ---------------- Kernel C: tag projection ----------------
__global__ __launch_bounds__(256) void tag_kernel(
    const float* __restrict__ w_tag, const float* __restrict__ b_tag)
{
    int t = blockIdx.x;
    __shared__ __align__(16) float row[2 * HDIM];
    int tid = threadIdx.x; // 256
    ((float4*)row)[tid] = ((const float4*)&g_lstm[t][0])[tid];
    __syncthreads();

    int lane8 = tid & 7;
    int k = tid >> 3;     // 0..31
    const float4* wr = (const float4*)(w_tag + (size_t)k * 2 * HDIM);
    const float4* r4 = (const float4*)row;
    float acc = 0.f;
#pragma unroll
    for (int i = 0; i < 32; i++) {
        float4 w = wr[lane8 + 8 * i];
        float4 x = r4[lane8 + 8 * i];
        acc = fmaf(w.x, x.x, acc);
        acc = fmaf(w.y, x.y, acc);
        acc = fmaf(w.z, x.z, acc);
        acc = fmaf(w.w, x.w, acc);
    }
    acc += __shfl_down_sync(0xffffffffu, acc, 4, 8);
    acc += __shfl_down_sync(0xffffffffu, acc, 2, 8);
    acc += __shfl_down_sync(0xffffffffu, acc, 1, 8);
    if (lane8 == 0) g_feats[t][k] = acc + b_tag[k];
}

// ---------------- Kernel D: Viterbi decode (one warp) ----------------
__global__ void viterbi_kernel(const float* __restrict__ trans,
                               float* __restrict__ out)
{
    __shared__ float fv[KTAG];
    __shared__ unsigned char bp[TT][KTAG];
    int tid = threadIdx.x;  // 32, thread = next-tag index

    float tr[KTAG];
#pragma unroll
    for (int p = 0; p < KTAG; p++) tr[p] = trans[tid * KTAG + p];
    float stoprow = trans[STOP_TAG * KTAG + tid];

    fv[tid] = (tid == START_TAG) ? 0.f : NEGV;
    __syncwarp();

    for (int t = 0; t < TT; t++) {
        float best = -3.4e38f;
        int bi = 0;
#pragma unroll
        for (int p = 0; p < KTAG; p++) {
            float sc = fv[p] + tr[p];
            if (sc > best) { best = sc; bi = p; }
        }
        bp[t][tid] = (unsigned char)bi;
        float nf = best + g_feats[t][tid];
        __syncwarp();
        fv[tid] = nf;
        __syncwarp();
    }

    float bv = fv[tid] + stoprow;
    int bidx = tid;
#pragma unroll
    for (int off = 16; off > 0; off >>= 1) {
        float ov = __shfl_down_sync(0xffffffffu, bv, off);
        int oi   = __shfl_down_sync(0xffffffffu, bidx, off);
        if (ov > bv || (ov == bv && oi < bidx)) { bv = ov; bidx = oi; }
    }
    bv   = __shfl_sync(0xffffffffu, bv, 0);
    bidx = __shfl_sync(0xffffffffu, bidx, 0);

    if (tid == 0) {
        out[0] = bv;                     // score
        out[TT] = (float)bidx;           // path[T-1] = best
        int tag = bidx;
        for (int t = TT - 1; t >= 1; t--) {
            tag = bp[t][tag];
            out[t] = (float)tag;         // path[t-1]
        }
    }
}

// ---------------- launch ----------------
extern "C" void kernel_launch(void* const* d_in, const int* in_sizes, int n_in,
                              void* d_out, int out_size)
{
    const int*   sentence = (const int*)d_in[0];
    const float* embed    = (const float*)d_in[1];
    const float* w_ih_f   = (const float*)d_in[2];
    const float* w_hh_f   = (const float*)d_in[3];
    const float* b_ih_f   = (const float*)d_in[4];
    const float* b_hh_f   = (const float*)d_in[5];
    const float* w_ih_b   = (const float*)d_in[6];
    const float* w_hh_b   = (const float*)d_in[7];
    const float* b_ih_b   = (const float*)d_in[8];
    const float* b_hh_b   = (const float*)d_in[9];
    const float* h0       = (const float*)d_in[10];
    const float* c0       = (const float*)d_in[11];
    const float* w_tag    = (const float*)d_in[12];
    const float* b_tag    = (const float*)d_in[13];
    const float* trans    = (const float*)d_in[14];
    float* out = (float*)d_out;

    // poison exchange slots: 131072 float4 / 256 = 512 blocks
    poison_kernel<<<512, 256>>>();

    dim3 ggrid(G4 / 128, TT / 128, 2);   // 16 x 4 x 2 = 128 blocks
    gemm_xw_kernel<<<ggrid, 256>>>(sentence, embed,
                                   w_ih_f, b_ih_f, b_hh_f,
                                   w_ih_b, b_ih_b, b_hh_b);

    lstm_kernel<<<2 * NBD, LSTM_THREADS>>>(w_hh_f, w_hh_b, h0, c0);

    tag_kernel<<<TT, 256>>>(w_tag, b_tag);

    viterbi_kernel<<<1, 32>>>(trans, out);
}